// round 16
// baseline (speedup 1.0000x reference)
#include <cuda_runtime.h>
#include <cuda_bf16.h>
#include <math.h>

#define B_  256
#define T_  256
#define E_  64
#define N_  512
#define V_  128
#define G4  2048   // 4*N
#define NBLK 128   // recurrence blocks
#define NWRK 20    // logits worker blocks
#define NTILES 512 // out tiles of 128 rows

#define KS_BF 520   // Wh SMEM stride in bf16: [col][k], padded (260 words % 32 == 4)
#define KS_W  260
#define HA_BF 72    // hA staging stride in bf16: [row][k], padded
#define HA_W  36
#define XZT_W 68    // xzTab stride in floats
#define Z_STRIDE 68 // z-exchange float stride

// SMEM byte offsets (recurrence)
#define OFF_WHI   0
#define OFF_WLO   (64 * KS_BF * 2)                // 66560
#define OFF_XZT   (2 * 64 * KS_BF * 2)            // 133120
#define OFF_XIDS  (OFF_XZT + 128 * XZT_W * 4)     // 167936
#define OFF_HA    (OFF_XIDS + 256)                // 168192
#define HA_BYTES  (64 * HA_BF * 2)                // 9216 (per plane; buffer = 2 planes)
#define SMEM_TOTAL_LSTM (OFF_HA + 4 * HA_BYTES)   // 205056

// worker path: 4 planes of [128][36 words] at smem base
#define GW 36
#define PLANE (128 * GW)

// ---- scratch (static device memory; no allocations) ----
__device__ float g_hs[(size_t)T_ * B_ * N_];   // [T,B,N] hidden states for final dense
__device__ float g_h[2][B_ * N_];              // ping-pong h
__device__ int   g_xt[T_ * B_];                // X transposed: [t][b]
__device__ unsigned g_flags[NBLK * 32];        // flags, 128B-padded

// ---------------------------------------------------------------------------
__device__ __forceinline__ float sigf(float x) {
    return __fdividef(1.f, 1.f + __expf(-x));
}

__device__ __forceinline__ float tanhf_fast(float x) {
    float t = __expf(-2.f * fabsf(x));
    float r = __fdividef(1.f - t, 1.f + t);
    return copysignf(r, x);
}

__device__ __forceinline__ void mma_bf16(float* d, const unsigned* a, const unsigned* b) {
    asm volatile(
        "mma.sync.aligned.m16n8k16.row.col.f32.bf16.bf16.f32 "
        "{%0,%1,%2,%3}, {%4,%5,%6,%7}, {%8,%9}, {%0,%1,%2,%3};"
        : "+f"(d[0]), "+f"(d[1]), "+f"(d[2]), "+f"(d[3])
        : "r"(a[0]), "r"(a[1]), "r"(a[2]), "r"(a[3]), "r"(b[0]), "r"(b[1]));
}

__device__ __forceinline__ void bf16_split(float x, __nv_bfloat16& hi, __nv_bfloat16& lo) {
    hi = __float2bfloat16(x);
    lo = __float2bfloat16(x - __bfloat162float(hi));
}

__device__ __forceinline__ unsigned pack_bf2(__nv_bfloat16 lo, __nv_bfloat16 hi) {
    unsigned short ul = __bfloat16_as_ushort(lo);
    unsigned short uh = __bfloat16_as_ushort(hi);
    return (unsigned)ul | ((unsigned)uh << 16);
}

__device__ __forceinline__ void split4(float4 v, uint2& hw, uint2& lw) {
    __nv_bfloat16 h0, l0, h1, l1, h2, l2, h3, l3;
    bf16_split(v.x, h0, l0); bf16_split(v.y, h1, l1);
    bf16_split(v.z, h2, l2); bf16_split(v.w, h3, l3);
    hw = make_uint2(pack_bf2(h0, h1), pack_bf2(h2, h3));
    lw = make_uint2(pack_bf2(l0, l1), pack_bf2(l2, l3));
}

__device__ __forceinline__ void wait_flag_ge(const unsigned* addr, unsigned tgt) {
    unsigned v;
    do {
        asm volatile("ld.global.acquire.gpu.u32 %0, [%1];"
                     : "=r"(v) : "l"(addr) : "memory");
        if (v >= tgt) break;
        __nanosleep(20);
    } while (true);
}

extern __shared__ char smem_raw[];

// ---------------------------------------------------------------------------
// init: load h_0, transpose X, reset flags
// ---------------------------------------------------------------------------
__global__ void init_kernel(const float* __restrict__ h0, const int* __restrict__ X) {
    int i = blockIdx.x * blockDim.x + threadIdx.x;
    if (i < B_ * N_) g_h[0][i] = h0[i];
    if (i < T_ * B_) {
        int t = i >> 8, b = i & 255;
        g_xt[i] = X[b * T_ + t];
    }
    if (i < NBLK) g_flags[i * 32] = 0u;
}

// ---------------------------------------------------------------------------
// worker GEMM core: block tile 128 rows x 128 cols, warp 32x64
// ---------------------------------------------------------------------------
__device__ __forceinline__ void gemm_chunk(const unsigned* AhiW, const unsigned* AloW,
                                           const unsigned* BhiW, const unsigned* BloW,
                                           int wr, int wc, int g4r, int lk,
                                           float acc[2][8][4]) {
#pragma unroll
    for (int k16 = 0; k16 < 4; k16++) {
        unsigned aHi[2][4], aLo[2][4];
#pragma unroll
        for (int f = 0; f < 2; f++) {
            int aw = (wr + f * 16 + g4r) * GW + lk + k16 * 8;
            aHi[f][0] = AhiW[aw];          aHi[f][1] = AhiW[aw + 8 * GW];
            aHi[f][2] = AhiW[aw + 4];      aHi[f][3] = AhiW[aw + 8 * GW + 4];
            aLo[f][0] = AloW[aw];          aLo[f][1] = AloW[aw + 8 * GW];
            aLo[f][2] = AloW[aw + 4];      aLo[f][3] = AloW[aw + 8 * GW + 4];
        }
#pragma unroll
        for (int sub = 0; sub < 8; sub++) {
            int col = wc + sub * 8 + g4r;
            int bw  = col * GW + lk + k16 * 8;
            unsigned bHi[2], bLo[2];
            bHi[0] = BhiW[bw]; bHi[1] = BhiW[bw + 4];
            bLo[0] = BloW[bw]; bLo[1] = BloW[bw + 4];
#pragma unroll
            for (int f = 0; f < 2; f++) {
                mma_bf16(acc[f][sub], aHi[f], bHi);
                mma_bf16(acc[f][sub], aHi[f], bLo);
                mma_bf16(acc[f][sub], aLo[f], bHi);
            }
        }
    }
}

// ---------------------------------------------------------------------------
// Fused persistent kernel:
//   blocks 0..127  : LSTM recurrence with per-chunk producer waits
//   blocks 128..147: logits workers (unchanged)
// ---------------------------------------------------------------------------
__global__ void __launch_bounds__(256, 1)
lstm_fused(const float* __restrict__ Wh, const float* __restrict__ c0,
           const float* __restrict__ Wx, const float* __restrict__ emb,
           const float* __restrict__ bias,
           const float* __restrict__ Wd, const float* __restrict__ bd,
           float*       __restrict__ out) {
    const int tid  = threadIdx.x;
    const int bid  = blockIdx.x;
    const int lane = tid & 31;
    const int wid  = tid >> 5;
    const int g4r  = lane >> 2;
    const int lk   = lane & 3;
    const int lx2  = lk * 2;

    if (bid >= NBLK) {
        // ================= logits worker =================
        const int w = bid - NBLK;
        unsigned* AhiW = (unsigned*)smem_raw;
        unsigned* AloW = AhiW + PLANE;
        unsigned* BhiW = AloW + PLANE;
        unsigned* BloW = BhiW + PLANE;

        const int wr = (wid & 3) * 32;
        const int wc = (wid >> 2) * 64;
        const int srow = tid >> 1;
        const int sqb  = (tid & 1) * 8;
        const int bc   = tid & 127;
        const int bkh  = tid >> 7;

        for (int tile = w; tile < NTILES; tile += NWRK) {
            const unsigned tgt = (unsigned)((tile >> 1) + 1);
            if (tid < NBLK)
                wait_flag_ge(&g_flags[tid * 32], tgt);
            __syncthreads();

            const int r0 = tile * 128;
            float acc[2][8][4];
#pragma unroll
            for (int f = 0; f < 2; f++)
#pragma unroll
                for (int s = 0; s < 8; s++)
#pragma unroll
                    for (int i = 0; i < 4; i++) acc[f][s][i] = 0.f;

            for (int kc = 0; kc < 8; kc++) {
#pragma unroll
                for (int q = 0; q < 8; q++) {
                    float4 v = __ldcg((const float4*)(g_hs + (size_t)(r0 + srow) * N_ + kc * 64 + (sqb + q) * 4));
                    uint2 hw, lw;
                    split4(v, hw, lw);
                    int widx = srow * GW + (sqb + q) * 2;
                    *(uint2*)(AhiW + widx) = hw;
                    *(uint2*)(AloW + widx) = lw;
                }
#pragma unroll
                for (int kk = 0; kk < 16; kk++) {
                    int k0 = kc * 64 + bkh * 32 + kk * 2;
                    float a = Wd[(size_t)k0 * V_ + bc];
                    float b = Wd[(size_t)(k0 + 1) * V_ + bc];
                    __nv_bfloat16 ha, la, hb, lb;
                    bf16_split(a, ha, la); bf16_split(b, hb, lb);
                    int widx = bc * GW + bkh * 16 + kk;
                    BhiW[widx] = pack_bf2(ha, hb);
                    BloW[widx] = pack_bf2(la, lb);
                }
                __syncthreads();

                gemm_chunk(AhiW, AloW, BhiW, BloW, wr, wc, g4r, lk, acc);
                __syncthreads();
            }

#pragma unroll
            for (int f = 0; f < 2; f++) {
                int rlo = r0 + wr + f * 16 + g4r;
                int t0 = rlo >> 8,        b0 = rlo & 255;
                int t1 = (rlo + 8) >> 8,  b1 = (rlo + 8) & 255;
                size_t o0 = ((size_t)b0 * T_ + t0) * V_;
                size_t o1 = ((size_t)b1 * T_ + t1) * V_;
#pragma unroll
                for (int sub = 0; sub < 8; sub++) {
                    int v = wc + sub * 8 + lx2;
                    float2 bb = *(const float2*)(bd + v);
                    *(float2*)(out + o0 + v) = make_float2(acc[f][sub][0] + bb.x, acc[f][sub][1] + bb.y);
                    *(float2*)(out + o1 + v) = make_float2(acc[f][sub][2] + bb.x, acc[f][sub][3] + bb.y);
                }
            }
        }
        return;
    }

    // ================= LSTM recurrence =================
    __nv_bfloat16* WhHi = (__nv_bfloat16*)(smem_raw + OFF_WHI);
    __nv_bfloat16* WhLo = (__nv_bfloat16*)(smem_raw + OFF_WLO);
    float* xzTab        = (float*)(smem_raw + OFF_XZT);
    int* xids           = (int*)(smem_raw + OFF_XIDS);
    char* hBase         = smem_raw + OFF_HA;   // buf0: hi,lo ; buf1: hi,lo

    const unsigned* WhHiW = (const unsigned*)WhHi;
    const unsigned* WhLoW = (const unsigned*)WhLo;

    const int cg = bid & 31;          // n-group
    const int rg = bid >> 5;          // row-group
    const int n0 = cg * 16;
    const int r0 = rg * 64;
    const int wr = (wid & 3) * 16;    // warp row offset
    const int wc = (wid >> 2) * 32;   // warp col offset

    // ---- load + split Wh slice once: [col][k], col = g*16+j ----
    for (int idx = tid; idx < 512 * 16; idx += 256) {
        int k = idx >> 4, q = idx & 15;
        int g = q >> 2, jj = (q & 3) * 4;
        float4 w = *(const float4*)(Wh + (size_t)k * G4 + g * N_ + n0 + jj);
        int cb = g * 16 + jj;
        __nv_bfloat16 hi, lo;
        bf16_split(w.x, hi, lo); WhHi[(cb + 0) * KS_BF + k] = hi; WhLo[(cb + 0) * KS_BF + k] = lo;
        bf16_split(w.y, hi, lo); WhHi[(cb + 1) * KS_BF + k] = hi; WhLo[(cb + 1) * KS_BF + k] = lo;
        bf16_split(w.z, hi, lo); WhHi[(cb + 2) * KS_BF + k] = hi; WhLo[(cb + 2) * KS_BF + k] = lo;
        bf16_split(w.w, hi, lo); WhHi[(cb + 3) * KS_BF + k] = hi; WhLo[(cb + 3) * KS_BF + k] = lo;
    }

    // ---- precompute xzTab (fp32): stage emb fp32 in hA scratch ----
    {
        float* embF = (float*)hBase;   // [128][64] fp32
        for (int idx = tid; idx < 128 * 16; idx += 256) {
            int v = idx >> 4, jj = (idx & 15) * 4;
            *(float4*)(embF + v * 64 + jj) = *(const float4*)(emb + (size_t)v * E_ + jj);
        }
        __syncthreads();

        const int c     = tid & 63;
        const int gcol  = (c >> 4) * N_ + n0 + (c & 15);
        const int vBase = (tid >> 6) * 32;

        float a[32];
        float bv = bias[gcol];
#pragma unroll
        for (int v = 0; v < 32; v++) a[v] = bv;
        for (int e = 0; e < E_; e++) {
            float wx = Wx[(size_t)e * G4 + gcol];
#pragma unroll
            for (int v = 0; v < 32; v++)
                a[v] = fmaf(embF[(vBase + v) * 64 + e], wx, a[v]);
        }
        __syncthreads();
#pragma unroll
        for (int v = 0; v < 32; v++)
            xzTab[(vBase + v) * XZT_W + c] = a[v];
    }

    // ---- xids for t = 0 ----
    if (tid < 64) xids[tid] = g_xt[r0 + tid];

    // ---- cell state in registers ----
    const int prow = tid >> 2;
    const int pj0  = (tid & 3) * 4;
    float4 creg = *(const float4*)(c0 + (size_t)(r0 + prow) * N_ + n0 + pj0);

    __syncthreads();

    const int srow0 = tid >> 4;            // staging rows: +0,16,32,48
    const int skq   = tid & 15;            // k quad (4 bf16 = 2 words)
    const int aBase = (wr + g4r) * HA_W + lk;
    const int arow0 = wr + g4r;            // local mma rows arow0, arow0+8
    const int flagBase = rg * 32;

    for (int t = 0; t < T_; t++) {
        const float* __restrict__ h_in  = g_h[t & 1];
        float*       __restrict__ h_out = g_h[(t + 1) & 1];

        // ---- wait for chunk-0 producers (blocks cg=0..3 of this row group)
        //      to have finished step t-1 (flag >= t); trivial at t=0 ----
        if (tid < 4)
            wait_flag_ge(&g_flags[(flagBase + tid) * 32], (unsigned)t);
        __syncthreads();

        // ---- pf load chunk 0 ----
        float4 pf[4];
#pragma unroll
        for (int q = 0; q < 4; q++)
            pf[q] = __ldcg((const float4*)(h_in + (size_t)(r0 + srow0 + q * 16) * N_ + skq * 4));

        // ---- acc init: gather xz from table by vocab id ----
        float acc[4][4];
        {
            const float* row0 = xzTab + xids[arow0] * XZT_W;
            const float* row1 = xzTab + xids[arow0 + 8] * XZT_W;
#pragma unroll
            for (int sub = 0; sub < 4; sub++) {
                int c = wc + sub * 8 + lx2;
                float2 xlo = *(const float2*)(row0 + c);
                float2 xhi = *(const float2*)(row1 + c);
                acc[sub][0] = xlo.x; acc[sub][1] = xlo.y;
                acc[sub][2] = xhi.x; acc[sub][3] = xhi.y;
            }
        }

        // ---- GEMM over K=512 in 8 chunks of 64 with per-chunk waits ----
        for (int j = 0; j < 8; j++) {
            unsigned* sHiW = (unsigned*)(hBase + (j & 1) * 2 * HA_BYTES);
            unsigned* sLoW = sHiW + HA_BYTES / 4;
#pragma unroll
            for (int q = 0; q < 4; q++) {
                int row = srow0 + q * 16;
                uint2 hw, lw;
                split4(pf[q], hw, lw);
                int widx = row * HA_W + skq * 2;
                *(uint2*)(sHiW + widx) = hw;
                *(uint2*)(sLoW + widx) = lw;
            }
            // wait for producers of chunk j+1 (blocks cg = 4(j+1)..4(j+1)+3)
            if (j < 7 && tid < 4)
                wait_flag_ge(&g_flags[(flagBase + 4 * (j + 1) + tid) * 32], (unsigned)t);
            __syncthreads();
            if (j < 7) {
#pragma unroll
                for (int q = 0; q < 4; q++)
                    pf[q] = __ldcg((const float4*)(h_in + (size_t)(r0 + srow0 + q * 16) * N_ + (j + 1) * 64 + skq * 4));
            }

#pragma unroll
            for (int k16 = 0; k16 < 4; k16++) {
                const int aw = aBase + k16 * 8;
                unsigned aHi[4], aLo[4];
                aHi[0] = sHiW[aw];              aHi[1] = sHiW[aw + 8 * HA_W];
                aHi[2] = sHiW[aw + 4];          aHi[3] = sHiW[aw + 8 * HA_W + 4];
                aLo[0] = sLoW[aw];              aLo[1] = sLoW[aw + 8 * HA_W];
                aLo[2] = sLoW[aw + 4];          aLo[3] = sLoW[aw + 8 * HA_W + 4];
                const int kAbs = j * 32 + lk + k16 * 8;
#pragma unroll
                for (int sub = 0; sub < 4; sub++) {
                    const int col = wc + sub * 8 + g4r;
                    const int bw  = col * KS_W + kAbs;
                    unsigned bHi[2], bLo[2];
                    bHi[0] = WhHiW[bw]; bHi[1] = WhHiW[bw + 4];
                    bLo[0] = WhLoW[bw]; bLo[1] = WhLoW[bw + 4];
                    mma_bf16(acc[sub], aHi, bHi);
                    mma_bf16(acc[sub], aHi, bLo);
                    mma_bf16(acc[sub], aLo, bHi);
                }
            }
            // no tail sync: next stage targets the other buffer
        }

        // ---- exchange z through SMEM: last compute read buf1 -> z in buf0 ----
        float* zs = (float*)hBase;
        {
            const int rl = wr + g4r;
#pragma unroll
            for (int sub = 0; sub < 4; sub++) {
                int c = wc + sub * 8 + lx2;
                *(float2*)(zs + (size_t)rl * Z_STRIDE + c)       = make_float2(acc[sub][0], acc[sub][1]);
                *(float2*)(zs + (size_t)(rl + 8) * Z_STRIDE + c) = make_float2(acc[sub][2], acc[sub][3]);
            }
        }
        __syncthreads();

        // ---- pointwise gates + c/h update (fast math) ----
        {
            const float* zr = zs + (size_t)prow * Z_STRIDE + pj0;
            float4 zi = *(const float4*)(zr + 0);
            float4 zf = *(const float4*)(zr + 16);
            float4 zg = *(const float4*)(zr + 32);
            float4 zo = *(const float4*)(zr + 48);

            float4 hv;
            creg.x = sigf(zf.x) * creg.x + sigf(zi.x) * tanhf_fast(zg.x); hv.x = sigf(zo.x) * tanhf_fast(creg.x);
            creg.y = sigf(zf.y) * creg.y + sigf(zi.y) * tanhf_fast(zg.y); hv.y = sigf(zo.y) * tanhf_fast(creg.y);
            creg.z = sigf(zf.z) * creg.z + sigf(zi.z) * tanhf_fast(zg.z); hv.z = sigf(zo.z) * tanhf_fast(creg.z);
            creg.w = sigf(zf.w) * creg.w + sigf(zi.w) * tanhf_fast(zg.w); hv.w = sigf(zo.w) * tanhf_fast(creg.w);

            size_t off = (size_t)(r0 + prow) * N_ + n0 + pj0;
            *(float4*)(h_out + off) = hv;
            *(float4*)(g_hs + (size_t)t * B_ * N_ + off) = hv;
        }

        // ---- load next step's xids (read only after next head sync) ----
        if (t + 1 < T_ && tid < 64)
            xids[tid] = g_xt[(t + 1) * B_ + r0 + tid];

        // ---- publish flag t+1 (workers + peer chunk-waits consume it) ----
        __syncthreads();
        if (tid == 0) {
            asm volatile("st.global.release.gpu.u32 [%0], %1;"
                         :: "l"(&g_flags[bid * 32]), "r"((unsigned)(t + 1)) : "memory");
        }
    }
}

// ---------------------------------------------------------------------------
extern "C" void kernel_launch(void* const* d_in, const int* in_sizes, int n_in,
                              void* d_out, int out_size) {
    const int*   X    = (const int*)  d_in[0];
    const float* h0   = (const float*)d_in[1];
    const float* c0   = (const float*)d_in[2];
    const float* emb  = (const float*)d_in[3];
    const float* Wx   = (const float*)d_in[4];
    const float* Wh   = (const float*)d_in[5];
    const float* bias = (const float*)d_in[6];
    const float* Wd   = (const float*)d_in[7];
    const float* bd   = (const float*)d_in[8];
    float* out = (float*)d_out;

    cudaFuncSetAttribute(lstm_fused, cudaFuncAttributeMaxDynamicSharedMemorySize, SMEM_TOTAL_LSTM);

    init_kernel<<<(B_ * N_ + 255) / 256, 256>>>(h0, X);
    lstm_fused<<<NBLK + NWRK, 256, SMEM_TOTAL_LSTM>>>(Wh, c0, Wx, emb, bias, Wd, bd, out);
}

// round 17
// speedup vs baseline: 1.2491x; 1.2491x over previous
#include <cuda_runtime.h>
#include <cuda_bf16.h>
#include <math.h>

#define B_  256
#define T_  256
#define E_  64
#define N_  512
#define V_  128
#define G4  2048   // 4*N
#define NBLK 128   // recurrence blocks
#define NWRK 20    // logits worker blocks
#define NTILES 512 // out tiles of 128 rows

#define KS_BF 520   // Wh SMEM stride in bf16: [col][k], padded (260 words % 32 == 4)
#define KS_W  260
#define HA_BF 72    // hA staging stride in bf16: [row][k], padded
#define HA_W  36
#define XZT_W 68    // xzTab stride in floats
#define Z_STRIDE 68 // z-exchange float stride

// SMEM byte offsets (recurrence)
#define OFF_WHI   0
#define OFF_WLO   (64 * KS_BF * 2)                // 66560
#define OFF_XZT   (2 * 64 * KS_BF * 2)            // 133120
#define OFF_XIDS  (OFF_XZT + 128 * XZT_W * 4)     // 167936
#define OFF_HA    (OFF_XIDS + 256)                // 168192
#define HA_BYTES  (64 * HA_BF * 2)                // 9216 (per plane; buffer = 2 planes)
#define SMEM_TOTAL_LSTM (OFF_HA + 4 * HA_BYTES)   // 205056

// worker path: 4 planes of [128][36 words] at smem base
#define GW 36
#define PLANE (128 * GW)

// ---- scratch (static device memory; no allocations) ----
// unified h storage: plane p (rows p*B_ .. p*B_+255) = h after step p-1; plane 0 = h0
__device__ float g_hs[(size_t)(T_ + 1) * B_ * N_];
__device__ int   g_xt[T_ * B_];                // X transposed: [t][b]
__device__ unsigned g_flags[NBLK * 32];        // flags, 128B-padded

// ---------------------------------------------------------------------------
__device__ __forceinline__ float sigf(float x) {
    return __fdividef(1.f, 1.f + __expf(-x));
}

__device__ __forceinline__ float tanhf_fast(float x) {
    float t = __expf(-2.f * fabsf(x));
    float r = __fdividef(1.f - t, 1.f + t);
    return copysignf(r, x);
}

__device__ __forceinline__ void mma_bf16(float* d, const unsigned* a, const unsigned* b) {
    asm volatile(
        "mma.sync.aligned.m16n8k16.row.col.f32.bf16.bf16.f32 "
        "{%0,%1,%2,%3}, {%4,%5,%6,%7}, {%8,%9}, {%0,%1,%2,%3};"
        : "+f"(d[0]), "+f"(d[1]), "+f"(d[2]), "+f"(d[3])
        : "r"(a[0]), "r"(a[1]), "r"(a[2]), "r"(a[3]), "r"(b[0]), "r"(b[1]));
}

__device__ __forceinline__ void bf16_split(float x, __nv_bfloat16& hi, __nv_bfloat16& lo) {
    hi = __float2bfloat16(x);
    lo = __float2bfloat16(x - __bfloat162float(hi));
}

__device__ __forceinline__ unsigned pack_bf2(__nv_bfloat16 lo, __nv_bfloat16 hi) {
    unsigned short ul = __bfloat16_as_ushort(lo);
    unsigned short uh = __bfloat16_as_ushort(hi);
    return (unsigned)ul | ((unsigned)uh << 16);
}

__device__ __forceinline__ void split4(float4 v, uint2& hw, uint2& lw) {
    __nv_bfloat16 h0, l0, h1, l1, h2, l2, h3, l3;
    bf16_split(v.x, h0, l0); bf16_split(v.y, h1, l1);
    bf16_split(v.z, h2, l2); bf16_split(v.w, h3, l3);
    hw = make_uint2(pack_bf2(h0, h1), pack_bf2(h2, h3));
    lw = make_uint2(pack_bf2(l0, l1), pack_bf2(l2, l3));
}

__device__ __forceinline__ void wait_flag_ge(const unsigned* addr, unsigned tgt) {
    unsigned v;
    do {
        asm volatile("ld.global.acquire.gpu.u32 %0, [%1];"
                     : "=r"(v) : "l"(addr) : "memory");
        if (v >= tgt) break;
        __nanosleep(20);
    } while (true);
}

extern __shared__ char smem_raw[];

// ---------------------------------------------------------------------------
// init: load h_0 into plane 0, transpose X, reset flags
// ---------------------------------------------------------------------------
__global__ void init_kernel(const float* __restrict__ h0, const int* __restrict__ X) {
    int i = blockIdx.x * blockDim.x + threadIdx.x;
    if (i < B_ * N_) g_hs[i] = h0[i];
    if (i < T_ * B_) {
        int t = i >> 8, b = i & 255;
        g_xt[i] = X[b * T_ + t];
    }
    if (i < NBLK) g_flags[i * 32] = 0u;
}

// ---------------------------------------------------------------------------
// worker GEMM core: block tile 128 rows x 128 cols, warp 32x64
// ---------------------------------------------------------------------------
__device__ __forceinline__ void gemm_chunk(const unsigned* AhiW, const unsigned* AloW,
                                           const unsigned* BhiW, const unsigned* BloW,
                                           int wr, int wc, int g4r, int lk,
                                           float acc[2][8][4]) {
#pragma unroll
    for (int k16 = 0; k16 < 4; k16++) {
        unsigned aHi[2][4], aLo[2][4];
#pragma unroll
        for (int f = 0; f < 2; f++) {
            int aw = (wr + f * 16 + g4r) * GW + lk + k16 * 8;
            aHi[f][0] = AhiW[aw];          aHi[f][1] = AhiW[aw + 8 * GW];
            aHi[f][2] = AhiW[aw + 4];      aHi[f][3] = AhiW[aw + 8 * GW + 4];
            aLo[f][0] = AloW[aw];          aLo[f][1] = AloW[aw + 8 * GW];
            aLo[f][2] = AloW[aw + 4];      aLo[f][3] = AloW[aw + 8 * GW + 4];
        }
#pragma unroll
        for (int sub = 0; sub < 8; sub++) {
            int col = wc + sub * 8 + g4r;
            int bw  = col * GW + lk + k16 * 8;
            unsigned bHi[2], bLo[2];
            bHi[0] = BhiW[bw]; bHi[1] = BhiW[bw + 4];
            bLo[0] = BloW[bw]; bLo[1] = BloW[bw + 4];
#pragma unroll
            for (int f = 0; f < 2; f++) {
                mma_bf16(acc[f][sub], aHi[f], bHi);
                mma_bf16(acc[f][sub], aHi[f], bLo);
                mma_bf16(acc[f][sub], aLo[f], bHi);
            }
        }
    }
}

// ---------------------------------------------------------------------------
// Fused persistent kernel (R15 structure):
//   blocks 0..127  : LSTM recurrence, bulk row-group barrier per step
//   blocks 128..147: logits workers
// ---------------------------------------------------------------------------
__global__ void __launch_bounds__(256, 1)
lstm_fused(const float* __restrict__ Wh, const float* __restrict__ c0,
           const float* __restrict__ Wx, const float* __restrict__ emb,
           const float* __restrict__ bias,
           const float* __restrict__ Wd, const float* __restrict__ bd,
           float*       __restrict__ out) {
    const int tid  = threadIdx.x;
    const int bid  = blockIdx.x;
    const int lane = tid & 31;
    const int wid  = tid >> 5;
    const int g4r  = lane >> 2;
    const int lk   = lane & 3;
    const int lx2  = lk * 2;

    if (bid >= NBLK) {
        // ================= logits worker =================
        const int w = bid - NBLK;
        unsigned* AhiW = (unsigned*)smem_raw;
        unsigned* AloW = AhiW + PLANE;
        unsigned* BhiW = AloW + PLANE;
        unsigned* BloW = BhiW + PLANE;

        const int wr = (wid & 3) * 32;
        const int wc = (wid >> 2) * 64;
        const int srow = tid >> 1;
        const int sqb  = (tid & 1) * 8;
        const int bc   = tid & 127;
        const int bkh  = tid >> 7;

        for (int tile = w; tile < NTILES; tile += NWRK) {
            const unsigned tgt = (unsigned)((tile >> 1) + 1);
            if (tid < NBLK)
                wait_flag_ge(&g_flags[tid * 32], tgt);
            __syncthreads();

            const int r0 = tile * 128;
            // h(t) lives in plane t+1 -> shift rows by +B_
            const float* hsrc = g_hs + (size_t)(r0 + B_ + srow) * N_;

            float acc[2][8][4];
#pragma unroll
            for (int f = 0; f < 2; f++)
#pragma unroll
                for (int s = 0; s < 8; s++)
#pragma unroll
                    for (int i = 0; i < 4; i++) acc[f][s][i] = 0.f;

            for (int kc = 0; kc < 8; kc++) {
#pragma unroll
                for (int q = 0; q < 8; q++) {
                    float4 v = __ldcg((const float4*)(hsrc + kc * 64 + (sqb + q) * 4));
                    uint2 hw, lw;
                    split4(v, hw, lw);
                    int widx = srow * GW + (sqb + q) * 2;
                    *(uint2*)(AhiW + widx) = hw;
                    *(uint2*)(AloW + widx) = lw;
                }
#pragma unroll
                for (int kk = 0; kk < 16; kk++) {
                    int k0 = kc * 64 + bkh * 32 + kk * 2;
                    float a = Wd[(size_t)k0 * V_ + bc];
                    float b = Wd[(size_t)(k0 + 1) * V_ + bc];
                    __nv_bfloat16 ha, la, hb, lb;
                    bf16_split(a, ha, la); bf16_split(b, hb, lb);
                    int widx = bc * GW + bkh * 16 + kk;
                    BhiW[widx] = pack_bf2(ha, hb);
                    BloW[widx] = pack_bf2(la, lb);
                }
                __syncthreads();

                gemm_chunk(AhiW, AloW, BhiW, BloW, wr, wc, g4r, lk, acc);
                __syncthreads();
            }

#pragma unroll
            for (int f = 0; f < 2; f++) {
                int rlo = r0 + wr + f * 16 + g4r;
                int t0 = rlo >> 8,        b0 = rlo & 255;
                int t1 = (rlo + 8) >> 8,  b1 = (rlo + 8) & 255;
                size_t o0 = ((size_t)b0 * T_ + t0) * V_;
                size_t o1 = ((size_t)b1 * T_ + t1) * V_;
#pragma unroll
                for (int sub = 0; sub < 8; sub++) {
                    int v = wc + sub * 8 + lx2;
                    float2 bb = *(const float2*)(bd + v);
                    *(float2*)(out + o0 + v) = make_float2(acc[f][sub][0] + bb.x, acc[f][sub][1] + bb.y);
                    *(float2*)(out + o1 + v) = make_float2(acc[f][sub][2] + bb.x, acc[f][sub][3] + bb.y);
                }
            }
        }
        return;
    }

    // ================= LSTM recurrence =================
    __nv_bfloat16* WhHi = (__nv_bfloat16*)(smem_raw + OFF_WHI);
    __nv_bfloat16* WhLo = (__nv_bfloat16*)(smem_raw + OFF_WLO);
    float* xzTab        = (float*)(smem_raw + OFF_XZT);
    int* xids           = (int*)(smem_raw + OFF_XIDS);
    char* hBase         = smem_raw + OFF_HA;   // buf0: hi,lo ; buf1: hi,lo

    const unsigned* WhHiW = (const unsigned*)WhHi;
    const unsigned* WhLoW = (const unsigned*)WhLo;

    const int cg = bid & 31;          // n-group
    const int rg = bid >> 5;          // row-group
    const int n0 = cg * 16;
    const int r0 = rg * 64;
    const int wr = (wid & 3) * 16;    // warp row offset
    const int wc = (wid >> 2) * 32;   // warp col offset

    // ---- load + split Wh slice once: [col][k], col = g*16+j ----
    for (int idx = tid; idx < 512 * 16; idx += 256) {
        int k = idx >> 4, q = idx & 15;
        int g = q >> 2, jj = (q & 3) * 4;
        float4 w = *(const float4*)(Wh + (size_t)k * G4 + g * N_ + n0 + jj);
        int cb = g * 16 + jj;
        __nv_bfloat16 hi, lo;
        bf16_split(w.x, hi, lo); WhHi[(cb + 0) * KS_BF + k] = hi; WhLo[(cb + 0) * KS_BF + k] = lo;
        bf16_split(w.y, hi, lo); WhHi[(cb + 1) * KS_BF + k] = hi; WhLo[(cb + 1) * KS_BF + k] = lo;
        bf16_split(w.z, hi, lo); WhHi[(cb + 2) * KS_BF + k] = hi; WhLo[(cb + 2) * KS_BF + k] = lo;
        bf16_split(w.w, hi, lo); WhHi[(cb + 3) * KS_BF + k] = hi; WhLo[(cb + 3) * KS_BF + k] = lo;
    }

    // ---- precompute xzTab (fp32): stage emb fp32 in hA scratch ----
    {
        float* embF = (float*)hBase;   // [128][64] fp32
        for (int idx = tid; idx < 128 * 16; idx += 256) {
            int v = idx >> 4, jj = (idx & 15) * 4;
            *(float4*)(embF + v * 64 + jj) = *(const float4*)(emb + (size_t)v * E_ + jj);
        }
        __syncthreads();

        const int c     = tid & 63;
        const int gcol  = (c >> 4) * N_ + n0 + (c & 15);
        const int vBase = (tid >> 6) * 32;

        float a[32];
        float bv = bias[gcol];
#pragma unroll
        for (int v = 0; v < 32; v++) a[v] = bv;
        for (int e = 0; e < E_; e++) {
            float wx = Wx[(size_t)e * G4 + gcol];
#pragma unroll
            for (int v = 0; v < 32; v++)
                a[v] = fmaf(embF[(vBase + v) * 64 + e], wx, a[v]);
        }
        __syncthreads();
#pragma unroll
        for (int v = 0; v < 32; v++)
            xzTab[(vBase + v) * XZT_W + c] = a[v];
    }

    // ---- xids for t = 0 ----
    if (tid < 64) xids[tid] = g_xt[r0 + tid];

    // ---- cell state in registers ----
    const int prow = tid >> 2;
    const int pj0  = (tid & 3) * 4;
    float4 creg = *(const float4*)(c0 + (size_t)(r0 + prow) * N_ + n0 + pj0);

    __syncthreads();

    const int srow0 = tid >> 4;            // staging rows: +0,16,32,48
    const int skq   = tid & 15;            // k quad (4 bf16 = 2 words)
    const int aBase = (wr + g4r) * HA_W + lk;
    const int arow0 = wr + g4r;            // local mma rows arow0, arow0+8
    const int flagBase = rg * 32;

    for (int t = 0; t < T_; t++) {
        // h(t-1..) planes: h_in = plane t, h_out = plane t+1
        const float* __restrict__ h_in  = g_hs + (size_t)t * B_ * N_;
        float*       __restrict__ h_out = g_hs + (size_t)(t + 1) * B_ * N_;

        // ---- acc init: gather xz from table by vocab id ----
        float acc[4][4];
        {
            const float* row0 = xzTab + xids[arow0] * XZT_W;
            const float* row1 = xzTab + xids[arow0 + 8] * XZT_W;
#pragma unroll
            for (int sub = 0; sub < 4; sub++) {
                int c = wc + sub * 8 + lx2;
                float2 xlo = *(const float2*)(row0 + c);
                float2 xhi = *(const float2*)(row1 + c);
                acc[sub][0] = xlo.x; acc[sub][1] = xlo.y;
                acc[sub][2] = xhi.x; acc[sub][3] = xhi.y;
            }
        }

        // ---- GEMM over K=512 in 8 chunks of 64, double-buffered staging ----
        float4 pf[4];
#pragma unroll
        for (int q = 0; q < 4; q++)
            pf[q] = __ldcg((const float4*)(h_in + (size_t)(r0 + srow0 + q * 16) * N_ + skq * 4));

        for (int j = 0; j < 8; j++) {
            unsigned* sHiW = (unsigned*)(hBase + (j & 1) * 2 * HA_BYTES);
            unsigned* sLoW = sHiW + HA_BYTES / 4;
#pragma unroll
            for (int q = 0; q < 4; q++) {
                int row = srow0 + q * 16;
                uint2 hw, lw;
                split4(pf[q], hw, lw);
                int widx = row * HA_W + skq * 2;
                *(uint2*)(sHiW + widx) = hw;
                *(uint2*)(sLoW + widx) = lw;
            }
            if (j < 7) {
#pragma unroll
                for (int q = 0; q < 4; q++)
                    pf[q] = __ldcg((const float4*)(h_in + (size_t)(r0 + srow0 + q * 16) * N_ + (j + 1) * 64 + skq * 4));
            }
            __syncthreads();

#pragma unroll
            for (int k16 = 0; k16 < 4; k16++) {
                const int aw = aBase + k16 * 8;
                unsigned aHi[4], aLo[4];
                aHi[0] = sHiW[aw];              aHi[1] = sHiW[aw + 8 * HA_W];
                aHi[2] = sHiW[aw + 4];          aHi[3] = sHiW[aw + 8 * HA_W + 4];
                aLo[0] = sLoW[aw];              aLo[1] = sLoW[aw + 8 * HA_W];
                aLo[2] = sLoW[aw + 4];          aLo[3] = sLoW[aw + 8 * HA_W + 4];
                const int kAbs = j * 32 + lk + k16 * 8;
#pragma unroll
                for (int sub = 0; sub < 4; sub++) {
                    const int col = wc + sub * 8 + g4r;
                    const int bw  = col * KS_W + kAbs;
                    unsigned bHi[2], bLo[2];
                    bHi[0] = WhHiW[bw]; bHi[1] = WhHiW[bw + 4];
                    bLo[0] = WhLoW[bw]; bLo[1] = WhLoW[bw + 4];
                    mma_bf16(acc[sub], aHi, bHi);
                    mma_bf16(acc[sub], aHi, bLo);
                    mma_bf16(acc[sub], aLo, bHi);
                }
            }
            // no tail sync: next stage targets the other buffer
        }

        // ---- exchange z through SMEM: last compute read buf1 -> z in buf0 ----
        float* zs = (float*)hBase;
        {
            const int rl = wr + g4r;
#pragma unroll
            for (int sub = 0; sub < 4; sub++) {
                int c = wc + sub * 8 + lx2;
                *(float2*)(zs + (size_t)rl * Z_STRIDE + c)       = make_float2(acc[sub][0], acc[sub][1]);
                *(float2*)(zs + (size_t)(rl + 8) * Z_STRIDE + c) = make_float2(acc[sub][2], acc[sub][3]);
            }
        }
        __syncthreads();

        // ---- pointwise gates + c/h update (fast math); single h store ----
        {
            const float* zr = zs + (size_t)prow * Z_STRIDE + pj0;
            float4 zi = *(const float4*)(zr + 0);
            float4 zf = *(const float4*)(zr + 16);
            float4 zg = *(const float4*)(zr + 32);
            float4 zo = *(const float4*)(zr + 48);

            float4 hv;
            creg.x = sigf(zf.x) * creg.x + sigf(zi.x) * tanhf_fast(zg.x); hv.x = sigf(zo.x) * tanhf_fast(creg.x);
            creg.y = sigf(zf.y) * creg.y + sigf(zi.y) * tanhf_fast(zg.y); hv.y = sigf(zo.y) * tanhf_fast(creg.y);
            creg.z = sigf(zf.z) * creg.z + sigf(zi.z) * tanhf_fast(zg.z); hv.z = sigf(zo.z) * tanhf_fast(creg.z);
            creg.w = sigf(zf.w) * creg.w + sigf(zi.w) * tanhf_fast(zg.w); hv.w = sigf(zo.w) * tanhf_fast(creg.w);

            *(float4*)(h_out + (size_t)(r0 + prow) * N_ + n0 + pj0) = hv;
        }

        // ---- load next step's xids (consumed after the barrier) ----
        if (t + 1 < T_ && tid < 64)
            xids[tid] = g_xt[(t + 1) * B_ + r0 + tid];

        // ---- publish flag t+1 (always: workers need it for every t);
        //      wait on row-group flags only while more steps remain ----
        __syncthreads();
        if (tid == 0) {
            asm volatile("st.global.release.gpu.u32 [%0], %1;"
                         :: "l"(&g_flags[bid * 32]), "r"((unsigned)(t + 1)) : "memory");
        }
        if (t + 1 < T_) {
            if (tid < 32)
                wait_flag_ge(&g_flags[(flagBase + tid) * 32], (unsigned)(t + 1));
            __syncthreads();
        }
    }
}

// ---------------------------------------------------------------------------
extern "C" void kernel_launch(void* const* d_in, const int* in_sizes, int n_in,
                              void* d_out, int out_size) {
    const int*   X    = (const int*)  d_in[0];
    const float* h0   = (const float*)d_in[1];
    const float* c0   = (const float*)d_in[2];
    const float* emb  = (const float*)d_in[3];
    const float* Wx   = (const float*)d_in[4];
    const float* Wh   = (const float*)d_in[5];
    const float* bias = (const float*)d_in[6];
    const float* Wd   = (const float*)d_in[7];
    const float* bd   = (const float*)d_in[8];
    float* out = (float*)d_out;

    cudaFuncSetAttribute(lstm_fused, cudaFuncAttributeMaxDynamicSharedMemorySize, SMEM_TOTAL_LSTM);

    init_kernel<<<(B_ * N_ + 255) / 256, 256>>>(h0, X);
    lstm_fused<<<NBLK + NWRK, 256, SMEM_TOTAL_LSTM>>>(Wh, c0, Wx, emb, bias, Wd, bd, out);
}